// round 2
// baseline (speedup 1.0000x reference)
#include <cuda_runtime.h>

#define HH 256
#define WW 256
#define BB 8
#define IMG_PIX (HH*WW)          // 65536
#define NPIX (BB*IMG_PIX)        // 524288

static __device__ float  g_gray[2][NPIX];
static __device__ float  g_s[2][NPIX];
static __device__ float4 g_cst[NPIX];     // {dx, dy, rho_c+EPS, th}
static __device__ float  g_ig[NPIX];      // (grad>EPS) ? 1/grad : 0
static __device__ float2 g_u[2][NPIX];
static __device__ float4 g_p[2][NPIX];
static __device__ int    g_mn, g_mx;

__constant__ float GW[25] = {
    0.000874f, 0.006976f, 0.01386f,  0.006976f, 0.000874f,
    0.006976f, 0.0557f,   0.110656f, 0.0557f,   0.006976f,
    0.01386f,  0.110656f, 0.219833f, 0.110656f, 0.01386f,
    0.006976f, 0.0557f,   0.110656f, 0.0557f,   0.006976f,
    0.000874f, 0.006976f, 0.01386f,  0.006976f, 0.000874f
};

#define L_T    0.045f
#define THETA  0.3f
#define TAUT   0.8333333333333334f
#define EPSV   1e-12f

__device__ __forceinline__ float rsqrt_approx(float x){
    float y; asm("rsqrt.approx.f32 %0, %1;" : "=f"(y) : "f"(x)); return y;
}
__device__ __forceinline__ float rcp_approx(float x){
    float y; asm("rcp.approx.f32 %0, %1;" : "=f"(y) : "f"(x)); return y;
}

__global__ void k_init(){ g_mn = 0x7f7fffff; g_mx = 0; }

// gray conversion + global min/max reduction over BOTH images
__global__ __launch_bounds__(256) void k_gray(const float* __restrict__ x1,
                                              const float* __restrict__ x2)
{
    int idx = blockIdx.x*256 + threadIdx.x;     // < NPIX
    int b   = idx >> 16;
    int pix = idx & 65535;
    int o   = b*3*IMG_PIX + pix;
    float g1 = 0.114f*x1[o] + 0.587f*x1[o+IMG_PIX] + 0.299f*x1[o+2*IMG_PIX];
    float g2 = 0.114f*x2[o] + 0.587f*x2[o+IMG_PIX] + 0.299f*x2[o+2*IMG_PIX];
    g_gray[0][idx] = g1;
    g_gray[1][idx] = g2;
    float mn = fminf(g1, g2), mx = fmaxf(g1, g2);
    #pragma unroll
    for (int off = 16; off; off >>= 1){
        mn = fminf(mn, __shfl_xor_sync(0xffffffffu, mn, off));
        mx = fmaxf(mx, __shfl_xor_sync(0xffffffffu, mx, off));
    }
    __shared__ float smn[8], smx[8];
    int lane = threadIdx.x & 31, w = threadIdx.x >> 5;
    if (!lane){ smn[w] = mn; smx[w] = mx; }
    __syncthreads();
    if (threadIdx.x == 0){
        #pragma unroll
        for (int i = 1; i < 8; i++){ mn = fminf(mn, smn[i]); mx = fmaxf(mx, smx[i]); }
        atomicMin(&g_mn, __float_as_int(mn));   // all values >= 0: int order == float order
        atomicMax(&g_mx, __float_as_int(mx));
    }
}

// normalize + 5x5 gaussian (zero SAME padding)
__global__ __launch_bounds__(256) void k_smooth()
{
    int img = blockIdx.z >> 3;
    int b   = blockIdx.z & 7;
    const float* gsrc = g_gray[img] + b*IMG_PIX;
    float mn = __int_as_float(g_mn);
    float mx = __int_as_float(g_mx);
    float scale = 255.0f / (mx - mn);
    __shared__ float sn[36*36];
    int tx0 = blockIdx.x*32, ty0 = blockIdx.y*32;
    int tid = threadIdx.x;
    for (int idx = tid; idx < 36*36; idx += 256){
        int li = idx/36, lj = idx - li*36;
        int gi = ty0 + li - 2, gj = tx0 + lj - 2;
        float v = 0.f;
        if ((unsigned)gi < HH && (unsigned)gj < WW) v = (gsrc[gi*WW+gj] - mn)*scale;
        sn[idx] = v;
    }
    __syncthreads();
    int lj = tid & 31, li0 = tid >> 5;
    #pragma unroll
    for (int r = 0; r < 4; r++){
        int li = li0 + r*8;
        float acc = 0.f;
        #pragma unroll
        for (int a = 0; a < 5; a++)
            #pragma unroll
            for (int c = 0; c < 5; c++)
                acc += GW[a*5+c]*sn[(li+a)*36 + lj + c];
        g_s[img][b*IMG_PIX + (ty0+li)*WW + tx0+lj] = acc;
    }
}

// centered grad of s2, per-pixel constants, zero-init state
__global__ __launch_bounds__(256) void k_prep()
{
    int idx = blockIdx.x*256 + threadIdx.x;
    int b = idx >> 16, pix = idx & 65535;
    int i = pix >> 8, j = pix & 255;
    const float* s2 = g_s[1] + b*IMG_PIX;
    float c  = s2[pix];
    float xr = s2[i*WW + min(j+1, WW-1)];
    float xl = s2[i*WW + max(j-1, 0)];
    float yd = s2[min(i+1, HH-1)*WW + j];
    float yu = s2[max(i-1, 0)*WW + j];
    float dx = 0.5f*(xr - xl);
    float dy = 0.5f*(yd - yu);
    float grad = dx*dx + dy*dy + EPSV;
    float rho_c = c - g_s[0][idx] + EPSV;
    g_cst[idx] = make_float4(dx, dy, rho_c, L_T*grad);
    g_ig[idx]  = (grad > EPSV) ? (1.0f/grad) : 0.0f;
    g_u[0][idx] = make_float2(0.f, 0.f);
    g_p[0][idx] = make_float4(0.f, 0.f, 0.f, 0.f);
}

// one fused TV-L1 iteration: u-update (needs p at up/left) then p-update
// (needs u_new at down/right) on a 32x32 tile with 1-halo.
__global__ __launch_bounds__(256) void k_iter(int s, int last, float* __restrict__ out)
{
    __shared__ float4 sp[34*34];
    __shared__ float2 su[33*33];
    __shared__ float2 sun[33*33];

    const float4* __restrict__ p_in = g_p[s];
    const float2* __restrict__ u_in = g_u[s];
    float4* __restrict__ p_out = g_p[s^1];
    float2* __restrict__ u_out = g_u[s^1];

    const int tx0 = blockIdx.x*32, ty0 = blockIdx.y*32, b = blockIdx.z;
    const int base = b*IMG_PIX;
    const int tid = threadIdx.x;

    for (int idx = tid; idx < 34*34; idx += 256){
        int li = idx/34, lj = idx - li*34;
        int gi = ty0 + li - 1, gj = tx0 + lj - 1;
        float4 v = make_float4(0.f,0.f,0.f,0.f);
        if ((unsigned)gi < HH && (unsigned)gj < WW) v = p_in[base + gi*WW + gj];
        sp[idx] = v;
    }
    for (int idx = tid; idx < 33*33; idx += 256){
        int li = idx/33, lj = idx - li*33;
        int gi = ty0 + li, gj = tx0 + lj;
        float2 v = make_float2(0.f,0.f);
        if (gi < HH && gj < WW) v = u_in[base + gi*WW + gj];
        su[idx] = v;
    }
    __syncthreads();

    // u_new over tile + right/down halo (33x33)
    for (int idx = tid; idx < 33*33; idx += 256){
        int li = idx/33, lj = idx - li*33;
        int gi = ty0 + li, gj = tx0 + lj;
        float2 un = make_float2(0.f,0.f);
        if (gi < HH && gj < WW){
            int g = base + gi*WW + gj;
            float4 c = g_cst[g];
            float ig = g_ig[g];
            float2 u = su[idx];
            float rho = c.z + c.x*u.x + c.y*u.y;
            float th  = c.w;
            float coef;
            if      (rho < -th) coef =  L_T;
            else if (rho >  th) coef = -L_T;
            else                coef = -rho*ig;
            float4 pc = sp[(li+1)*34 + lj+1];
            float4 pl = sp[(li+1)*34 + lj];
            float4 pu = sp[li*34 + lj+1];
            float d1 = ((gj < WW-1)? pc.x : 0.f) - ((gj > 0)? pl.x : 0.f)
                     + ((gi < HH-1)? pc.y : 0.f) - ((gi > 0)? pu.y : 0.f);
            float d2 = ((gj < WW-1)? pc.z : 0.f) - ((gj > 0)? pl.z : 0.f)
                     + ((gi < HH-1)? pc.w : 0.f) - ((gi > 0)? pu.w : 0.f);
            un.x = coef*c.x + u.x + THETA*d1;
            un.y = coef*c.y + u.y + THETA*d2;
        }
        sun[idx] = un;
    }
    __syncthreads();

    // p_new + writes over the 32x32 interior
    for (int idx = tid; idx < 32*32; idx += 256){
        int li = idx >> 5, lj = idx & 31;
        int gi = ty0 + li, gj = tx0 + lj;
        float2 uc = sun[li*33 + lj];
        float2 ur = sun[li*33 + lj + 1];
        float2 ud = sun[(li+1)*33 + lj];
        float u1x = (gj < WW-1)? ur.x - uc.x : 0.f;
        float u2x = (gj < WW-1)? ur.y - uc.y : 0.f;
        float u1y = (gi < HH-1)? ud.x - uc.x : 0.f;
        float u2y = (gi < HH-1)? ud.y - uc.y : 0.f;
        float s1 = u1x*u1x + u1y*u1y + EPSV;
        float s2 = u2x*u2x + u2y*u2y + EPSV;
        float ng1 = 1.f + TAUT*(s1*rsqrt_approx(s1));
        float ng2 = 1.f + TAUT*(s2*rsqrt_approx(s2));
        float r1 = rcp_approx(ng1), r2 = rcp_approx(ng2);
        float4 p = sp[(li+1)*34 + lj+1];
        float4 pn = make_float4((p.x + TAUT*u1x)*r1, (p.y + TAUT*u1y)*r1,
                                (p.z + TAUT*u2x)*r2, (p.w + TAUT*u2y)*r2);
        int g = base + gi*WW + gj;
        p_out[g] = pn;
        u_out[g] = uc;
        if (last){
            float4 c = g_cst[g];
            float2 uo = su[li*33 + lj];              // u BEFORE this update (scan semantics)
            float rho = c.z + c.x*uo.x + c.y*uo.y;
            int ob = b*3*IMG_PIX + gi*WW + gj;
            out[ob]             = uc.x;
            out[ob +   IMG_PIX] = uc.y;
            out[ob + 2*IMG_PIX] = rho;
        }
    }
}

extern "C" void kernel_launch(void* const* d_in, const int* in_sizes, int n_in,
                              void* d_out, int out_size)
{
    const float* x1 = (const float*)d_in[0];
    const float* x2 = (const float*)d_in[1];
    float* out = (float*)d_out;

    k_init<<<1, 1>>>();
    k_gray<<<NPIX/256, 256>>>(x1, x2);
    dim3 gB(8, 8, 16);
    k_smooth<<<gB, 256>>>();
    k_prep<<<NPIX/256, 256>>>();
    dim3 gI(8, 8, 8);
    for (int it = 0; it < 30; ++it)
        k_iter<<<gI, 256>>>(it & 1, it == 29, out);
}